// round 2
// baseline (speedup 1.0000x reference)
#include <cuda_runtime.h>

// PMLoss: pose-matching loss.
// B=128 ROIs, C=22 classes, P=1024 points per model.
// Inputs (metadata order): prediction[B,4C], target[B,4C], weight[B,4C],
//                          points[C,P,3], symmetry[C]. Output: scalar f32.

#define NB 128
#define NC 22
#define NP 1024
#define SPLIT 4
#define PPB (NP / SPLIT)   // 256 predicted points per block
#define TPB 256

__device__ float g_partials[NB * SPLIT];

__device__ __forceinline__ void quat2mat(float w, float x, float y, float z,
                                         float* R) {
    R[0] = 1.f - 2.f * (y * y + z * z);
    R[1] = 2.f * (x * y - w * z);
    R[2] = 2.f * (x * z + w * y);
    R[3] = 2.f * (x * y + w * z);
    R[4] = 1.f - 2.f * (x * x + z * z);
    R[5] = 2.f * (y * z - w * x);
    R[6] = 2.f * (x * z - w * y);
    R[7] = 2.f * (y * z + w * x);
    R[8] = 1.f - 2.f * (x * x + y * y);
}

__global__ __launch_bounds__(TPB) void pm_main_kernel(
    const float* __restrict__ pred, const float* __restrict__ tgt,
    const float* __restrict__ wt, const float* __restrict__ pts,
    const float* __restrict__ sym) {
    __shared__ float4 s_pt[NP];      // target-rotated points: (x, y, z, |pt|^2)
    __shared__ float s_R[18];        // Rp (0..8), Rt (9..17)
    __shared__ int s_cls;
    __shared__ int s_issym;
    __shared__ float s_red[TPB / 32];

    const int b = blockIdx.x;
    const int sblk = blockIdx.y;
    const int tid = threadIdx.x;

    if (tid == 0) {
        // Active class: the (unique) slot whose weight is 1.
        int cls = 0;
#pragma unroll
        for (int c = NC - 1; c >= 1; c--)
            if (wt[b * 4 * NC + c * 4] > 0.5f) cls = c;
        s_cls = cls;
        s_issym = (sym[cls] > 0.0f) ? 1 : 0;

        const float* qp = pred + b * 4 * NC + cls * 4;
        float qw = qp[0], qx = qp[1], qy = qp[2], qz = qp[3];
        float inv = rsqrtf(qw * qw + qx * qx + qy * qy + qz * qz);
        quat2mat(qw * inv, qx * inv, qy * inv, qz * inv, s_R);

        const float* qt = tgt + b * 4 * NC + cls * 4;   // already unit-norm
        quat2mat(qt[0], qt[1], qt[2], qt[3], s_R + 9);
    }
    __syncthreads();

    const int cls = s_cls;
    const int issym = s_issym;
    const float* __restrict__ mp = pts + (size_t)cls * NP * 3;

    // Compute target-rotated points for the whole model into shared (SoA float4).
    {
        float Rt0 = s_R[9], Rt1 = s_R[10], Rt2 = s_R[11];
        float Rt3 = s_R[12], Rt4 = s_R[13], Rt5 = s_R[14];
        float Rt6 = s_R[15], Rt7 = s_R[16], Rt8 = s_R[17];
#pragma unroll
        for (int q = tid; q < NP; q += TPB) {
            float x = mp[3 * q + 0], y = mp[3 * q + 1], z = mp[3 * q + 2];
            float tx = Rt0 * x + Rt1 * y + Rt2 * z;
            float ty = Rt3 * x + Rt4 * y + Rt5 * z;
            float tz = Rt6 * x + Rt7 * y + Rt8 * z;
            s_pt[q] = make_float4(tx, ty, tz, tx * tx + ty * ty + tz * tz);
        }
    }
    float Rp0 = s_R[0], Rp1 = s_R[1], Rp2 = s_R[2];
    float Rp3 = s_R[3], Rp4 = s_R[4], Rp5 = s_R[5];
    float Rp6 = s_R[6], Rp7 = s_R[7], Rp8 = s_R[8];
    __syncthreads();

    // Predicted-rotated point for this thread's p.
    const int p = sblk * PPB + tid;
    float x = mp[3 * p + 0], y = mp[3 * p + 1], z = mp[3 * p + 2];
    float ppx = Rp0 * x + Rp1 * y + Rp2 * z;
    float ppy = Rp3 * x + Rp4 * y + Rp5 * z;
    float ppz = Rp6 * x + Rp7 * y + Rp8 * z;

    float d;
    if (!issym) {
        float4 t = s_pt[p];
        float dx = ppx - t.x, dy = ppy - t.y, dz = ppz - t.z;
        d = dx * dx + dy * dy + dz * dz;
    } else {
        // d2(p,q) = |pp|^2 + |pt_q|^2 - 2 pp.pt_q.
        // Fold -2 into pp; add |pp|^2 after the min (constant per p).
        float a2x = -2.f * ppx, a2y = -2.f * ppy, a2z = -2.f * ppz;
        float m = 3.402823466e38f;
#pragma unroll 8
        for (int q = 0; q < NP; q++) {
            float4 t = s_pt[q];          // broadcast LDS.128
            float v = fmaf(a2x, t.x, t.w);
            v = fmaf(a2y, t.y, v);
            v = fmaf(a2z, t.z, v);
            m = fminf(m, v);
        }
        d = m + (ppx * ppx + ppy * ppy + ppz * ppz);
    }

    // Deterministic block reduction.
#pragma unroll
    for (int o = 16; o > 0; o >>= 1) d += __shfl_down_sync(0xffffffffu, d, o);
    if ((tid & 31) == 0) s_red[tid >> 5] = d;
    __syncthreads();
    if (tid < TPB / 32) {
        d = s_red[tid];
#pragma unroll
        for (int o = (TPB / 64); o > 0; o >>= 1)
            d += __shfl_down_sync(0xffu, d, o);
        if (tid == 0) g_partials[b * SPLIT + sblk] = d;
    }
}

__global__ __launch_bounds__(NB* SPLIT) void pm_reduce_kernel(
    float* __restrict__ out) {
    __shared__ float s_red[(NB * SPLIT) / 32];
    const int tid = threadIdx.x;
    float v = g_partials[tid];
#pragma unroll
    for (int o = 16; o > 0; o >>= 1) v += __shfl_down_sync(0xffffffffu, v, o);
    if ((tid & 31) == 0) s_red[tid >> 5] = v;
    __syncthreads();
    if (tid < (NB * SPLIT) / 32) {
        v = s_red[tid];
#pragma unroll
        for (int o = (NB * SPLIT) / 64; o > 0; o >>= 1)
            v += __shfl_down_sync(0xffffu, v, o);
        if (tid == 0) out[0] = v * (1.0f / (2.0f * NB * NP));
    }
}

extern "C" void kernel_launch(void* const* d_in, const int* in_sizes, int n_in,
                              void* d_out, int out_size) {
    const float* pred = (const float*)d_in[0];
    const float* tgt  = (const float*)d_in[1];
    const float* wt   = (const float*)d_in[2];
    const float* pts  = (const float*)d_in[3];
    const float* sym  = (const float*)d_in[4];
    float* out = (float*)d_out;

    dim3 grid(NB, SPLIT);
    pm_main_kernel<<<grid, TPB>>>(pred, tgt, wt, pts, sym);
    pm_reduce_kernel<<<1, NB * SPLIT>>>(out);
}

// round 3
// speedup vs baseline: 1.5955x; 1.5955x over previous
#include <cuda_runtime.h>

// PMLoss: pose-matching loss. B=128 ROIs, C=22 classes, P=1024 points.
// K1 (setup): per-ROI class/quat->mat, non-symmetric pointwise loss inline,
//             compacts symmetric ROIs into a list (consecutive heavy blocks).
// K2 (sym):   nearest-neighbor min over 1024x1024 with packed f32x2 FMA.
// K3 (reduce): deterministic fixed-slot sum; resets the sym counter.

#define NB 128
#define NC 22
#define NP 1024
#define CH 8                // chunks (over p) per symmetric ROI
#define PPB (NP / CH)       // 128 predicted points per heavy block
#define TPB 128

__device__ float g_partials[NB * CH];
__device__ int   g_sym_list[NB];
__device__ int   g_nsym = 0;        // reset at end of reduce each run
__device__ int   g_cls[NB];
__device__ float g_Rp[NB][9];
__device__ float g_Rt[NB][9];

__device__ __forceinline__ void quat2mat(float w, float x, float y, float z,
                                         float* R) {
    R[0] = 1.f - 2.f * (y * y + z * z);
    R[1] = 2.f * (x * y - w * z);
    R[2] = 2.f * (x * z + w * y);
    R[3] = 2.f * (x * y + w * z);
    R[4] = 1.f - 2.f * (x * x + z * z);
    R[5] = 2.f * (y * z - w * x);
    R[6] = 2.f * (x * z - w * y);
    R[7] = 2.f * (y * z + w * x);
    R[8] = 1.f - 2.f * (x * x + y * y);
}

__device__ __forceinline__ unsigned long long ffma2(unsigned long long a,
                                                    unsigned long long b,
                                                    unsigned long long c) {
    unsigned long long d;
    asm("fma.rn.f32x2 %0, %1, %2, %3;" : "=l"(d) : "l"(a), "l"(b), "l"(c));
    return d;
}
__device__ __forceinline__ unsigned long long pack2(float a, float b) {
    unsigned long long r;
    asm("mov.b64 %0, {%1, %2};" : "=l"(r) : "f"(a), "f"(b));
    return r;
}
__device__ __forceinline__ float2 unpack2(unsigned long long v) {
    float2 r;
    asm("mov.b64 {%0, %1}, %2;" : "=f"(r.x), "=f"(r.y) : "l"(v));
    return r;
}

__device__ __forceinline__ float block_reduce_128(float d, float* s_red,
                                                  int tid) {
#pragma unroll
    for (int o = 16; o > 0; o >>= 1) d += __shfl_down_sync(0xffffffffu, d, o);
    if ((tid & 31) == 0) s_red[tid >> 5] = d;
    __syncthreads();
    if (tid < 4) {
        d = s_red[tid];
        d += __shfl_down_sync(0xfu, d, 2);
        d += __shfl_down_sync(0xfu, d, 1);
    }
    return d;
}

// ---------------- K1: setup + non-symmetric loss ----------------
__global__ __launch_bounds__(TPB) void pm_setup_kernel(
    const float* __restrict__ pred, const float* __restrict__ tgt,
    const float* __restrict__ wt, const float* __restrict__ pts,
    const float* __restrict__ sym) {
    __shared__ float sR[18];
    __shared__ int s_cls, s_issym;
    __shared__ float s_red[4];

    const int b = blockIdx.x;
    const int tid = threadIdx.x;

    if (tid == 0) {
        int cls = 0;
#pragma unroll
        for (int c = 1; c < NC; c++)
            if (wt[b * 4 * NC + c * 4] > 0.5f) { cls = c; break; }
        s_cls = cls;
        g_cls[b] = cls;
        int issym = (sym[cls] > 0.0f) ? 1 : 0;
        s_issym = issym;

        const float* qp = pred + b * 4 * NC + cls * 4;
        float qw = qp[0], qx = qp[1], qy = qp[2], qz = qp[3];
        float inv = rsqrtf(qw * qw + qx * qx + qy * qy + qz * qz);
        quat2mat(qw * inv, qx * inv, qy * inv, qz * inv, sR);
        const float* qt = tgt + b * 4 * NC + cls * 4;   // unit-norm already
        quat2mat(qt[0], qt[1], qt[2], qt[3], sR + 9);
#pragma unroll
        for (int i = 0; i < 9; i++) {
            g_Rp[b][i] = sR[i];
            g_Rt[b][i] = sR[9 + i];
        }
        if (issym) {
            int k = atomicAdd(&g_nsym, 1);
            g_sym_list[k] = b;
        }
    }
    __syncthreads();
    if (s_issym) return;   // heavy kernel owns this ROI's partial slots

    // Non-symmetric: sum_p |(Rp - Rt) x_p|^2  (fold the subtraction).
    float D0 = sR[0] - sR[9],  D1 = sR[1] - sR[10], D2 = sR[2] - sR[11];
    float D3 = sR[3] - sR[12], D4 = sR[4] - sR[13], D5 = sR[5] - sR[14];
    float D6 = sR[6] - sR[15], D7 = sR[7] - sR[16], D8 = sR[8] - sR[17];
    const float* __restrict__ mp = pts + (size_t)s_cls * NP * 3;

    float acc = 0.f;
#pragma unroll 4
    for (int p = tid; p < NP; p += TPB) {
        float x = mp[3 * p + 0], y = mp[3 * p + 1], z = mp[3 * p + 2];
        float dx = D0 * x + D1 * y + D2 * z;
        float dy = D3 * x + D4 * y + D5 * z;
        float dz = D6 * x + D7 * y + D8 * z;
        acc += dx * dx + dy * dy + dz * dz;
    }
    float tot = block_reduce_128(acc, s_red, tid);
    if (tid == 0) g_partials[b * CH] = tot;
    else if (tid < CH) g_partials[b * CH + tid] = 0.f;  // zero unused slots
}

// ---------------- K2: symmetric nearest-neighbor ----------------
__global__ __launch_bounds__(TPB) void pm_sym_kernel(
    const float* __restrict__ pts) {
    const int ri = blockIdx.x / CH;
    if (ri >= g_nsym) return;
    const int chunk = blockIdx.x % CH;

    // Pair-packed target points: sA pair j = {x_{2j}, x_{2j+1}, y_{2j}, y_{2j+1}}
    //                            sB pair j = {z_{2j}, z_{2j+1}, w_{2j}, w_{2j+1}}
    __shared__ float sA[NP * 2];
    __shared__ float sB[NP * 2];
    __shared__ float s_red[4];

    const int tid = threadIdx.x;
    const int b = g_sym_list[ri];
    const int cls = g_cls[b];
    const float* __restrict__ mp = pts + (size_t)cls * NP * 3;

    {
        float T0 = g_Rt[b][0], T1 = g_Rt[b][1], T2 = g_Rt[b][2];
        float T3 = g_Rt[b][3], T4 = g_Rt[b][4], T5 = g_Rt[b][5];
        float T6 = g_Rt[b][6], T7 = g_Rt[b][7], T8 = g_Rt[b][8];
#pragma unroll
        for (int q = tid; q < NP; q += TPB) {
            float x = mp[3 * q + 0], y = mp[3 * q + 1], z = mp[3 * q + 2];
            float tx = T0 * x + T1 * y + T2 * z;
            float ty = T3 * x + T4 * y + T5 * z;
            float tz = T6 * x + T7 * y + T8 * z;
            int j = q >> 1, h = q & 1;
            sA[4 * j + h] = tx;
            sA[4 * j + 2 + h] = ty;
            sB[4 * j + h] = tz;
            sB[4 * j + 2 + h] = tx * tx + ty * ty + tz * tz;
        }
    }

    // This thread's predicted-rotated point.
    const int p = chunk * PPB + tid;
    float ppx, ppy, ppz;
    {
        float P0 = g_Rp[b][0], P1 = g_Rp[b][1], P2 = g_Rp[b][2];
        float P3 = g_Rp[b][3], P4 = g_Rp[b][4], P5 = g_Rp[b][5];
        float P6 = g_Rp[b][6], P7 = g_Rp[b][7], P8 = g_Rp[b][8];
        float x = mp[3 * p + 0], y = mp[3 * p + 1], z = mp[3 * p + 2];
        ppx = P0 * x + P1 * y + P2 * z;
        ppy = P3 * x + P4 * y + P5 * z;
        ppz = P6 * x + P7 * y + P8 * z;
    }
    __syncthreads();

    const unsigned long long ax2 = pack2(-2.f * ppx, -2.f * ppx);
    const unsigned long long ay2 = pack2(-2.f * ppy, -2.f * ppy);
    const unsigned long long az2 = pack2(-2.f * ppz, -2.f * ppz);

    const ulonglong2* __restrict__ pA = (const ulonglong2*)sA;
    const ulonglong2* __restrict__ pB = (const ulonglong2*)sB;

    float mlo = 3.402823466e38f, mhi = 3.402823466e38f;
#pragma unroll 8
    for (int j = 0; j < NP / 2; j++) {
        ulonglong2 A = pA[j];   // {xx, yy}
        ulonglong2 Bv = pB[j];  // {zz, ww}
        unsigned long long v = ffma2(ax2, A.x, Bv.y);  // -2*ppx*tx + |t|^2
        v = ffma2(ay2, A.y, v);
        v = ffma2(az2, Bv.x, v);
        float2 vf = unpack2(v);
        mlo = fminf(mlo, vf.x);
        mhi = fminf(mhi, vf.y);
    }
    float d = fminf(mlo, mhi) + (ppx * ppx + ppy * ppy + ppz * ppz);

    float tot = block_reduce_128(d, s_red, tid);
    if (tid == 0) g_partials[b * CH + chunk] = tot;
}

// ---------------- K3: final reduction ----------------
__global__ __launch_bounds__(512) void pm_reduce_kernel(float* __restrict__ out) {
    __shared__ float s_red[16];
    const int tid = threadIdx.x;
    if (tid == 0) g_nsym = 0;   // reset for next graph replay
    float v = g_partials[tid] + g_partials[tid + 512];
#pragma unroll
    for (int o = 16; o > 0; o >>= 1) v += __shfl_down_sync(0xffffffffu, v, o);
    if ((tid & 31) == 0) s_red[tid >> 5] = v;
    __syncthreads();
    if (tid < 16) {
        v = s_red[tid];
#pragma unroll
        for (int o = 8; o > 0; o >>= 1) v += __shfl_down_sync(0xffffu, v, o);
        if (tid == 0) out[0] = v * (1.0f / (2.0f * NB * NP));
    }
}

extern "C" void kernel_launch(void* const* d_in, const int* in_sizes, int n_in,
                              void* d_out, int out_size) {
    const float* pred = (const float*)d_in[0];
    const float* tgt  = (const float*)d_in[1];
    const float* wt   = (const float*)d_in[2];
    const float* pts  = (const float*)d_in[3];
    const float* sym  = (const float*)d_in[4];
    float* out = (float*)d_out;

    pm_setup_kernel<<<NB, TPB>>>(pred, tgt, wt, pts, sym);
    pm_sym_kernel<<<NB * CH, TPB>>>(pts);
    pm_reduce_kernel<<<1, 512>>>(out);
}

// round 4
// speedup vs baseline: 1.6184x; 1.0144x over previous
#include <cuda_runtime.h>

// PMLoss fused single-kernel. B=128 ROIs, C=22 classes, P=1024 points.
// grid = 1024 blocks: b = blk/8, chunk = blk%8 (128 points per chunk).
// Each block self-contains setup (warp-ballot class find + quat->mat),
// computes its loss piece, and the last-finishing block reduces all partials.

#define NB 128
#define NC 22
#define NP 1024
#define CH 8
#define PPB (NP / CH)     // 128
#define TPB 128
#define GRID (NB * CH)    // 1024

__device__ float g_partials[GRID];
__device__ unsigned int g_ticket = 0;

__device__ __forceinline__ void quat2mat(float w, float x, float y, float z,
                                         float* R) {
    R[0] = 1.f - 2.f * (y * y + z * z);
    R[1] = 2.f * (x * y - w * z);
    R[2] = 2.f * (x * z + w * y);
    R[3] = 2.f * (x * y + w * z);
    R[4] = 1.f - 2.f * (x * x + z * z);
    R[5] = 2.f * (y * z - w * x);
    R[6] = 2.f * (x * z - w * y);
    R[7] = 2.f * (y * z + w * x);
    R[8] = 1.f - 2.f * (x * x + y * y);
}

__device__ __forceinline__ unsigned long long ffma2(unsigned long long a,
                                                    unsigned long long b,
                                                    unsigned long long c) {
    unsigned long long d;
    asm("fma.rn.f32x2 %0, %1, %2, %3;" : "=l"(d) : "l"(a), "l"(b), "l"(c));
    return d;
}
__device__ __forceinline__ unsigned long long pack2(float a, float b) {
    unsigned long long r;
    asm("mov.b64 %0, {%1, %2};" : "=l"(r) : "f"(a), "f"(b));
    return r;
}
__device__ __forceinline__ float2 unpack2(unsigned long long v) {
    float2 r;
    asm("mov.b64 {%0, %1}, %2;" : "=f"(r.x), "=f"(r.y) : "l"(v));
    return r;
}

__device__ __forceinline__ float block_reduce_128(float d, float* s_red,
                                                  int tid) {
#pragma unroll
    for (int o = 16; o > 0; o >>= 1) d += __shfl_down_sync(0xffffffffu, d, o);
    if ((tid & 31) == 0) s_red[tid >> 5] = d;
    __syncthreads();
    if (tid < 4) {
        d = s_red[tid];
        d += __shfl_down_sync(0xfu, d, 2);
        d += __shfl_down_sync(0xfu, d, 1);
    }
    return d;
}

__global__ __launch_bounds__(TPB) void pm_fused_kernel(
    const float* __restrict__ pred, const float* __restrict__ tgt,
    const float* __restrict__ wt, const float* __restrict__ pts,
    const float* __restrict__ sym, float* __restrict__ out) {
    // Pair-packed target points: sA pair j = {x2j, x2j+1, y2j, y2j+1}
    //                            sB pair j = {z2j, z2j+1, w2j, w2j+1}
    __shared__ float sA[NP * 2];
    __shared__ float sB[NP * 2];
    __shared__ float sR[18];          // Rp 0..8, Rt 9..17
    __shared__ int s_cls, s_issym;
    __shared__ float s_red[4];

    const int b = blockIdx.x / CH;
    const int chunk = blockIdx.x % CH;
    const int tid = threadIdx.x;

    // ---- setup: parallel class find (warp 0), quat->mat (lane 0) ----
    if (tid < 32) {
        bool hit = (tid >= 1) && (tid < NC) &&
                   (wt[b * 4 * NC + 4 * tid] > 0.5f);
        unsigned m = __ballot_sync(0xffffffffu, hit);
        if (tid == 0) {
            int cls = m ? (__ffs(m) - 1) : 0;
            s_cls = cls;
            s_issym = (sym[cls] > 0.0f) ? 1 : 0;
            const float* qp = pred + b * 4 * NC + cls * 4;
            float qw = qp[0], qx = qp[1], qy = qp[2], qz = qp[3];
            float inv = rsqrtf(qw * qw + qx * qx + qy * qy + qz * qz);
            quat2mat(qw * inv, qx * inv, qy * inv, qz * inv, sR);
            const float* qt = tgt + b * 4 * NC + cls * 4;  // unit-norm
            quat2mat(qt[0], qt[1], qt[2], qt[3], sR + 9);
        }
    }
    __syncthreads();

    const int cls = s_cls;
    const float* __restrict__ mp = pts + (size_t)cls * NP * 3;
    const int p = chunk * PPB + tid;   // this thread's predicted point
    float d;

    if (!s_issym) {
        // Pointwise: |(Rp - Rt) x|^2 for this thread's point only.
        float D0 = sR[0] - sR[9],  D1 = sR[1] - sR[10], D2 = sR[2] - sR[11];
        float D3 = sR[3] - sR[12], D4 = sR[4] - sR[13], D5 = sR[5] - sR[14];
        float D6 = sR[6] - sR[15], D7 = sR[7] - sR[16], D8 = sR[8] - sR[17];
        float x = mp[3 * p + 0], y = mp[3 * p + 1], z = mp[3 * p + 2];
        float dx = D0 * x + D1 * y + D2 * z;
        float dy = D3 * x + D4 * y + D5 * z;
        float dz = D6 * x + D7 * y + D8 * z;
        d = dx * dx + dy * dy + dz * dz;
    } else {
        // Fill target-rotated points (pair-packed) into shared.
        {
            float T0 = sR[9],  T1 = sR[10], T2 = sR[11];
            float T3 = sR[12], T4 = sR[13], T5 = sR[14];
            float T6 = sR[15], T7 = sR[16], T8 = sR[17];
#pragma unroll
            for (int q = tid; q < NP; q += TPB) {
                float x = mp[3 * q + 0], y = mp[3 * q + 1], z = mp[3 * q + 2];
                float tx = T0 * x + T1 * y + T2 * z;
                float ty = T3 * x + T4 * y + T5 * z;
                float tz = T6 * x + T7 * y + T8 * z;
                int j = q >> 1, h = q & 1;
                sA[4 * j + h] = tx;
                sA[4 * j + 2 + h] = ty;
                sB[4 * j + h] = tz;
                sB[4 * j + 2 + h] = tx * tx + ty * ty + tz * tz;
            }
        }
        float ppx, ppy, ppz;
        {
            float P0 = sR[0], P1 = sR[1], P2 = sR[2];
            float P3 = sR[3], P4 = sR[4], P5 = sR[5];
            float P6 = sR[6], P7 = sR[7], P8 = sR[8];
            float x = mp[3 * p + 0], y = mp[3 * p + 1], z = mp[3 * p + 2];
            ppx = P0 * x + P1 * y + P2 * z;
            ppy = P3 * x + P4 * y + P5 * z;
            ppz = P6 * x + P7 * y + P8 * z;
        }
        __syncthreads();

        const unsigned long long ax2 = pack2(-2.f * ppx, -2.f * ppx);
        const unsigned long long ay2 = pack2(-2.f * ppy, -2.f * ppy);
        const unsigned long long az2 = pack2(-2.f * ppz, -2.f * ppz);
        const ulonglong2* __restrict__ pA = (const ulonglong2*)sA;
        const ulonglong2* __restrict__ pB = (const ulonglong2*)sB;

        float mlo = 3.402823466e38f, mhi = 3.402823466e38f;
#pragma unroll 8
        for (int j = 0; j < NP / 2; j++) {
            ulonglong2 A = pA[j];    // {xx, yy}
            ulonglong2 Bv = pB[j];   // {zz, ww}
            unsigned long long v = ffma2(ax2, A.x, Bv.y);
            v = ffma2(ay2, A.y, v);
            v = ffma2(az2, Bv.x, v);
            float2 vf = unpack2(v);
            mlo = fminf(mlo, vf.x);
            mhi = fminf(mhi, vf.y);
        }
        d = fminf(mlo, mhi) + (ppx * ppx + ppy * ppy + ppz * ppz);
    }

    // ---- block partial ----
    float tot = block_reduce_128(d, s_red, tid);
    __shared__ int s_last;
    if (tid == 0) {
        g_partials[blockIdx.x] = tot;
        __threadfence();
        unsigned t = atomicAdd(&g_ticket, 1u);
        s_last = (t == GRID - 1) ? 1 : 0;
    }
    __syncthreads();

    // ---- last block: deterministic fixed-order global reduction ----
    if (s_last) {
        __threadfence();   // acquire
        float v = 0.f;
#pragma unroll
        for (int i = 0; i < GRID / TPB; i++)
            v += __ldcg(&g_partials[tid + i * TPB]);
        float total = block_reduce_128(v, s_red, tid);
        if (tid == 0) {
            out[0] = total * (1.0f / (2.0f * NB * NP));
            g_ticket = 0;   // reset for next graph replay
        }
    }
}

extern "C" void kernel_launch(void* const* d_in, const int* in_sizes, int n_in,
                              void* d_out, int out_size) {
    const float* pred = (const float*)d_in[0];
    const float* tgt  = (const float*)d_in[1];
    const float* wt   = (const float*)d_in[2];
    const float* pts  = (const float*)d_in[3];
    const float* sym  = (const float*)d_in[4];
    float* out = (float*)d_out;

    pm_fused_kernel<<<GRID, TPB>>>(pred, tgt, wt, pts, sym, out);
}

// round 5
// speedup vs baseline: 1.7062x; 1.0542x over previous
#include <cuda_runtime.h>

// PMLoss fused single-kernel. B=128 ROIs, C=22 classes, P=1024 points.
// grid = 512 blocks: b = blk/4, chunk = blk%4 (256 points per chunk,
// 2 points per thread -> each shared-memory read of target data feeds 2 p's).
// Last-finishing block reduces all partials in fixed order (deterministic).

#define NB 128
#define NC 22
#define NP 1024
#define CH 4
#define PPB (NP / CH)     // 256
#define TPB 128
#define GRID (NB * CH)    // 512

__device__ float g_partials[GRID];
__device__ unsigned int g_ticket = 0;

__device__ __forceinline__ void quat2mat(float w, float x, float y, float z,
                                         float* R) {
    R[0] = 1.f - 2.f * (y * y + z * z);
    R[1] = 2.f * (x * y - w * z);
    R[2] = 2.f * (x * z + w * y);
    R[3] = 2.f * (x * y + w * z);
    R[4] = 1.f - 2.f * (x * x + z * z);
    R[5] = 2.f * (y * z - w * x);
    R[6] = 2.f * (x * z - w * y);
    R[7] = 2.f * (y * z + w * x);
    R[8] = 1.f - 2.f * (x * x + y * y);
}

__device__ __forceinline__ unsigned long long ffma2(unsigned long long a,
                                                    unsigned long long b,
                                                    unsigned long long c) {
    unsigned long long d;
    asm("fma.rn.f32x2 %0, %1, %2, %3;" : "=l"(d) : "l"(a), "l"(b), "l"(c));
    return d;
}
__device__ __forceinline__ unsigned long long pack2(float a, float b) {
    unsigned long long r;
    asm("mov.b64 %0, {%1, %2};" : "=l"(r) : "f"(a), "f"(b));
    return r;
}
__device__ __forceinline__ float2 unpack2(unsigned long long v) {
    float2 r;
    asm("mov.b64 {%0, %1}, %2;" : "=f"(r.x), "=f"(r.y) : "l"(v));
    return r;
}

__device__ __forceinline__ float block_reduce_128(float d, float* s_red,
                                                  int tid) {
#pragma unroll
    for (int o = 16; o > 0; o >>= 1) d += __shfl_down_sync(0xffffffffu, d, o);
    if ((tid & 31) == 0) s_red[tid >> 5] = d;
    __syncthreads();
    if (tid < 4) {
        d = s_red[tid];
        d += __shfl_down_sync(0xfu, d, 2);
        d += __shfl_down_sync(0xfu, d, 1);
    }
    return d;
}

__global__ __launch_bounds__(TPB) void pm_fused_kernel(
    const float* __restrict__ pred, const float* __restrict__ tgt,
    const float* __restrict__ wt, const float* __restrict__ pts,
    const float* __restrict__ sym, float* __restrict__ out) {
    // Pair-packed target points: sA pair j = {x2j, x2j+1, y2j, y2j+1}
    //                            sB pair j = {z2j, z2j+1, w2j, w2j+1}
    __shared__ float sA[NP * 2];
    __shared__ float sB[NP * 2];
    __shared__ float sR[18];          // Rp 0..8, Rt 9..17
    __shared__ int s_cls, s_issym;
    __shared__ float s_red[4];

    const int b = blockIdx.x / CH;
    const int chunk = blockIdx.x % CH;
    const int tid = threadIdx.x;

    // ---- setup: parallel class find (warp 0), quat->mat (lane 0) ----
    if (tid < 32) {
        bool hit = (tid >= 1) && (tid < NC) &&
                   (wt[b * 4 * NC + 4 * tid] > 0.5f);
        unsigned m = __ballot_sync(0xffffffffu, hit);
        if (tid == 0) {
            int cls = m ? (__ffs(m) - 1) : 0;
            s_cls = cls;
            s_issym = (sym[cls] > 0.0f) ? 1 : 0;
            const float* qp = pred + b * 4 * NC + cls * 4;
            float qw = qp[0], qx = qp[1], qy = qp[2], qz = qp[3];
            float inv = rsqrtf(qw * qw + qx * qx + qy * qy + qz * qz);
            quat2mat(qw * inv, qx * inv, qy * inv, qz * inv, sR);
            const float* qt = tgt + b * 4 * NC + cls * 4;  // unit-norm
            quat2mat(qt[0], qt[1], qt[2], qt[3], sR + 9);
        }
    }
    __syncthreads();

    const int cls = s_cls;
    const float* __restrict__ mp = pts + (size_t)cls * NP * 3;
    // This thread's two predicted points.
    const int p0 = chunk * PPB + tid;        // [0,128) within chunk
    const int p1 = p0 + TPB;                 // [128,256) within chunk
    float d;

    if (!s_issym) {
        // Pointwise: |(Rp - Rt) x|^2 for both points.
        float D0 = sR[0] - sR[9],  D1 = sR[1] - sR[10], D2 = sR[2] - sR[11];
        float D3 = sR[3] - sR[12], D4 = sR[4] - sR[13], D5 = sR[5] - sR[14];
        float D6 = sR[6] - sR[15], D7 = sR[7] - sR[16], D8 = sR[8] - sR[17];
        d = 0.f;
#pragma unroll
        for (int pi = 0; pi < 2; pi++) {
            int p = pi ? p1 : p0;
            float x = mp[3 * p + 0], y = mp[3 * p + 1], z = mp[3 * p + 2];
            float dx = D0 * x + D1 * y + D2 * z;
            float dy = D3 * x + D4 * y + D5 * z;
            float dz = D6 * x + D7 * y + D8 * z;
            d += dx * dx + dy * dy + dz * dz;
        }
    } else {
        // Fill target-rotated points (pair-packed) into shared.
        {
            float T0 = sR[9],  T1 = sR[10], T2 = sR[11];
            float T3 = sR[12], T4 = sR[13], T5 = sR[14];
            float T6 = sR[15], T7 = sR[16], T8 = sR[17];
#pragma unroll
            for (int q = tid; q < NP; q += TPB) {
                float x = mp[3 * q + 0], y = mp[3 * q + 1], z = mp[3 * q + 2];
                float tx = T0 * x + T1 * y + T2 * z;
                float ty = T3 * x + T4 * y + T5 * z;
                float tz = T6 * x + T7 * y + T8 * z;
                int j = q >> 1, h = q & 1;
                sA[4 * j + h] = tx;
                sA[4 * j + 2 + h] = ty;
                sB[4 * j + h] = tz;
                sB[4 * j + 2 + h] = tx * tx + ty * ty + tz * tz;
            }
        }
        // Predicted-rotated points.
        float px0, py0, pz0, px1, py1, pz1;
        {
            float P0 = sR[0], P1 = sR[1], P2 = sR[2];
            float P3 = sR[3], P4 = sR[4], P5 = sR[5];
            float P6 = sR[6], P7 = sR[7], P8 = sR[8];
            float x = mp[3 * p0 + 0], y = mp[3 * p0 + 1], z = mp[3 * p0 + 2];
            px0 = P0 * x + P1 * y + P2 * z;
            py0 = P3 * x + P4 * y + P5 * z;
            pz0 = P6 * x + P7 * y + P8 * z;
            x = mp[3 * p1 + 0]; y = mp[3 * p1 + 1]; z = mp[3 * p1 + 2];
            px1 = P0 * x + P1 * y + P2 * z;
            py1 = P3 * x + P4 * y + P5 * z;
            pz1 = P6 * x + P7 * y + P8 * z;
        }
        __syncthreads();

        const unsigned long long ax0 = pack2(-2.f * px0, -2.f * px0);
        const unsigned long long ay0 = pack2(-2.f * py0, -2.f * py0);
        const unsigned long long az0 = pack2(-2.f * pz0, -2.f * pz0);
        const unsigned long long ax1 = pack2(-2.f * px1, -2.f * px1);
        const unsigned long long ay1 = pack2(-2.f * py1, -2.f * py1);
        const unsigned long long az1 = pack2(-2.f * pz1, -2.f * pz1);
        const ulonglong2* __restrict__ pA = (const ulonglong2*)sA;
        const ulonglong2* __restrict__ pB = (const ulonglong2*)sB;

        const float INF = 3.402823466e38f;
        // 4 independent min chains per point (chain depth 256).
        float m0a = INF, m0b = INF, m0c = INF, m0d = INF;
        float m1a = INF, m1b = INF, m1c = INF, m1d = INF;
#pragma unroll 4
        for (int j = 0; j < NP / 4; j++) {
            ulonglong2 A0 = pA[2 * j];       // {xx, yy} q-pair 2j
            ulonglong2 B0 = pB[2 * j];       // {zz, ww}
            ulonglong2 A1 = pA[2 * j + 1];   // q-pair 2j+1
            ulonglong2 B1 = pB[2 * j + 1];

            unsigned long long v;
            float2 vf;
            // p0 vs q-pair 0
            v = ffma2(ax0, A0.x, B0.y);
            v = ffma2(ay0, A0.y, v);
            v = ffma2(az0, B0.x, v);
            vf = unpack2(v);
            m0a = fminf(m0a, vf.x);
            m0b = fminf(m0b, vf.y);
            // p1 vs q-pair 0
            v = ffma2(ax1, A0.x, B0.y);
            v = ffma2(ay1, A0.y, v);
            v = ffma2(az1, B0.x, v);
            vf = unpack2(v);
            m1a = fminf(m1a, vf.x);
            m1b = fminf(m1b, vf.y);
            // p0 vs q-pair 1
            v = ffma2(ax0, A1.x, B1.y);
            v = ffma2(ay0, A1.y, v);
            v = ffma2(az0, B1.x, v);
            vf = unpack2(v);
            m0c = fminf(m0c, vf.x);
            m0d = fminf(m0d, vf.y);
            // p1 vs q-pair 1
            v = ffma2(ax1, A1.x, B1.y);
            v = ffma2(ay1, A1.y, v);
            v = ffma2(az1, B1.x, v);
            vf = unpack2(v);
            m1c = fminf(m1c, vf.x);
            m1d = fminf(m1d, vf.y);
        }
        float d0 = fminf(fminf(m0a, m0b), fminf(m0c, m0d)) +
                   (px0 * px0 + py0 * py0 + pz0 * pz0);
        float d1 = fminf(fminf(m1a, m1b), fminf(m1c, m1d)) +
                   (px1 * px1 + py1 * py1 + pz1 * pz1);
        d = d0 + d1;
    }

    // ---- block partial ----
    float tot = block_reduce_128(d, s_red, tid);
    __shared__ int s_last;
    if (tid == 0) {
        g_partials[blockIdx.x] = tot;
        __threadfence();
        unsigned t = atomicAdd(&g_ticket, 1u);
        s_last = (t == GRID - 1) ? 1 : 0;
    }
    __syncthreads();

    // ---- last block: deterministic fixed-order global reduction ----
    if (s_last) {
        __threadfence();   // acquire
        float v = 0.f;
#pragma unroll
        for (int i = 0; i < GRID / TPB; i++)
            v += __ldcg(&g_partials[tid + i * TPB]);
        float total = block_reduce_128(v, s_red, tid);
        if (tid == 0) {
            out[0] = total * (1.0f / (2.0f * NB * NP));
            g_ticket = 0;   // reset for next graph replay
        }
    }
}

extern "C" void kernel_launch(void* const* d_in, const int* in_sizes, int n_in,
                              void* d_out, int out_size) {
    const float* pred = (const float*)d_in[0];
    const float* tgt  = (const float*)d_in[1];
    const float* wt   = (const float*)d_in[2];
    const float* pts  = (const float*)d_in[3];
    const float* sym  = (const float*)d_in[4];
    float* out = (float*)d_out;

    pm_fused_kernel<<<GRID, TPB>>>(pred, tgt, wt, pts, sym, out);
}